// round 1
// baseline (speedup 1.0000x reference)
#include <cuda_runtime.h>

#define BATCH 4
#define SEQ   2048
#define DIM   768
#define NHEAD 12
#define HDIM  64
#define QKVC  (3*DIM)            // 2304
#define ROWS  (BATCH*SEQ)        // 8192
#define ATT_SCALE 0.125f         // 1/sqrt(64)

// Scratch (allocation-free rule: __device__ globals)
__device__ float g_qkv[(size_t)ROWS * QKVC];   // [B*N, 3*H*D]  (q|k|v per row)
__device__ float g_att[(size_t)ROWS * DIM];    // [B*N, H*D]    attention output

// ---------------------------------------------------------------------------
// 128x128x8 register-blocked fp32 GEMM. A:[M,K] row-major, B:[K,N] row-major.
// 256 threads, 8x8 micro-tile per thread. Optional bias add on epilogue.
// M%128==0, N%128==0, K%8==0 (all true for our shapes).
// ---------------------------------------------------------------------------
__global__ __launch_bounds__(256) void sgemm128(
    const float* __restrict__ A, const float* __restrict__ B,
    const float* __restrict__ bias, float* __restrict__ C,
    int M, int N, int K, int addBias)
{
    __shared__ float As[8][128];   // transposed A tile: As[k][m]
    __shared__ float Bs[8][128];

    const int tid = threadIdx.x;
    const int bm = blockIdx.y * 128;
    const int bn = blockIdx.x * 128;
    const int tx = tid & 15;        // 0..15 -> col group
    const int ty = tid >> 4;        // 0..15 -> row group

    const int arow = tid >> 1;           // 0..127
    const int acol = (tid & 1) * 4;      // 0 or 4
    const int brow = tid >> 5;           // 0..7
    const int bcol = (tid & 31) * 4;     // 0..124

    const float* Aptr = A + (size_t)(bm + arow) * K + acol;
    const float* Bptr = B + (size_t)brow * N + bn + bcol;

    float acc[8][8];
    #pragma unroll
    for (int i = 0; i < 8; i++)
        #pragma unroll
        for (int j = 0; j < 8; j++) acc[i][j] = 0.f;

    for (int k0 = 0; k0 < K; k0 += 8) {
        float4 a = *(const float4*)(Aptr + k0);
        float4 b = *(const float4*)(Bptr + (size_t)k0 * N);
        As[acol + 0][arow] = a.x;
        As[acol + 1][arow] = a.y;
        As[acol + 2][arow] = a.z;
        As[acol + 3][arow] = a.w;
        *(float4*)&Bs[brow][bcol] = b;
        __syncthreads();

        #pragma unroll
        for (int kk = 0; kk < 8; kk++) {
            float ar[8], br[8];
            *(float4*)&ar[0] = *(const float4*)&As[kk][ty * 8];
            *(float4*)&ar[4] = *(const float4*)&As[kk][ty * 8 + 4];
            *(float4*)&br[0] = *(const float4*)&Bs[kk][tx * 8];
            *(float4*)&br[4] = *(const float4*)&Bs[kk][tx * 8 + 4];
            #pragma unroll
            for (int i = 0; i < 8; i++)
                #pragma unroll
                for (int j = 0; j < 8; j++)
                    acc[i][j] += ar[i] * br[j];
        }
        __syncthreads();
    }

    #pragma unroll
    for (int i = 0; i < 8; i++) {
        float* crow = C + (size_t)(bm + ty * 8 + i) * N + bn + tx * 8;
        #pragma unroll
        for (int j4 = 0; j4 < 2; j4++) {
            float4 v;
            v.x = acc[i][j4 * 4 + 0];
            v.y = acc[i][j4 * 4 + 1];
            v.z = acc[i][j4 * 4 + 2];
            v.w = acc[i][j4 * 4 + 3];
            if (addBias) {
                const float* bp = bias + bn + tx * 8 + j4 * 4;
                v.x += bp[0]; v.y += bp[1]; v.z += bp[2]; v.w += bp[3];
            }
            *(float4*)(crow + j4 * 4) = v;
        }
    }
}

// ---------------------------------------------------------------------------
// Flash-style attention: 1 thread = 1 query row. q[64]+acc[64] in registers,
// K/V tiles of 32 keys staged in shared (broadcast reads), online softmax
// merged per 8-key sub-chunk (keeps s[] small + code size under I$ limits).
// Grid: (SEQ/128, BATCH*NHEAD), 128 threads.
// ---------------------------------------------------------------------------
__global__ __launch_bounds__(128) void attn_kernel()
{
    const int bh = blockIdx.y;            // 0..47
    const int b  = bh / NHEAD;
    const int h  = bh - b * NHEAD;
    const int qidx = blockIdx.x * 128 + threadIdx.x;   // query row in [0,SEQ)

    __shared__ float Ksh[32][64];
    __shared__ float Vsh[32][64];

    // Load q row (pre-scaled)
    float q[64];
    {
        const float* qptr = &g_qkv[((size_t)(b * SEQ + qidx)) * QKVC + h * HDIM];
        #pragma unroll
        for (int d4 = 0; d4 < 16; d4++) {
            float4 v = *(const float4*)(qptr + d4 * 4);
            q[d4 * 4 + 0] = v.x * ATT_SCALE;
            q[d4 * 4 + 1] = v.y * ATT_SCALE;
            q[d4 * 4 + 2] = v.z * ATT_SCALE;
            q[d4 * 4 + 3] = v.w * ATT_SCALE;
        }
    }

    float acc[64];
    #pragma unroll
    for (int d = 0; d < 64; d++) acc[d] = 0.f;
    float m = -1e30f, l = 0.f;

    const float* kbase = &g_qkv[((size_t)(b * SEQ)) * QKVC + DIM + h * HDIM];
    const float* vbase = kbase + DIM;

    for (int k0 = 0; k0 < SEQ; k0 += 32) {
        // Cooperative tile load: 512 float4 per tile, 4 per thread
        #pragma unroll
        for (int it = 0; it < 4; it++) {
            int idx = threadIdx.x + it * 128;     // 0..511
            int key = idx >> 4;
            int d4  = idx & 15;
            ((float4*)Ksh)[idx] = *(const float4*)(kbase + (size_t)(k0 + key) * QKVC + d4 * 4);
            ((float4*)Vsh)[idx] = *(const float4*)(vbase + (size_t)(k0 + key) * QKVC + d4 * 4);
        }
        __syncthreads();

        for (int jc = 0; jc < 4; jc++) {           // 4 sub-chunks of 8 keys
            float s[8];
            #pragma unroll
            for (int j = 0; j < 8; j++) {
                const float4* kr = (const float4*)&Ksh[jc * 8 + j][0];
                float s0 = 0.f, s1 = 0.f, s2 = 0.f, s3 = 0.f;  // 4 chains
                #pragma unroll
                for (int d4 = 0; d4 < 16; d4++) {
                    float4 kv = kr[d4];
                    s0 += q[d4 * 4 + 0] * kv.x;
                    s1 += q[d4 * 4 + 1] * kv.y;
                    s2 += q[d4 * 4 + 2] * kv.z;
                    s3 += q[d4 * 4 + 3] * kv.w;
                }
                s[j] = (s0 + s1) + (s2 + s3);
            }
            float tmax = s[0];
            #pragma unroll
            for (int j = 1; j < 8; j++) tmax = fmaxf(tmax, s[j]);
            float m_new = fmaxf(m, tmax);
            float corr = __expf(m - m_new);
            l *= corr;
            #pragma unroll
            for (int d = 0; d < 64; d++) acc[d] *= corr;
            #pragma unroll
            for (int j = 0; j < 8; j++) {
                float p = __expf(s[j] - m_new);
                l += p;
                const float4* vr = (const float4*)&Vsh[jc * 8 + j][0];
                #pragma unroll
                for (int d4 = 0; d4 < 16; d4++) {
                    float4 vv = vr[d4];
                    acc[d4 * 4 + 0] += p * vv.x;
                    acc[d4 * 4 + 1] += p * vv.y;
                    acc[d4 * 4 + 2] += p * vv.z;
                    acc[d4 * 4 + 3] += p * vv.w;
                }
            }
            m = m_new;
        }
        __syncthreads();
    }

    const float inv = 1.f / l;
    float* optr = &g_att[((size_t)(b * SEQ + qidx)) * DIM + h * HDIM];
    #pragma unroll
    for (int d4 = 0; d4 < 16; d4++) {
        float4 v;
        v.x = acc[d4 * 4 + 0] * inv;
        v.y = acc[d4 * 4 + 1] * inv;
        v.z = acc[d4 * 4 + 2] * inv;
        v.w = acc[d4 * 4 + 3] * inv;
        *(float4*)(optr + d4 * 4) = v;
    }
}

// ---------------------------------------------------------------------------
extern "C" void kernel_launch(void* const* d_in, const int* in_sizes, int n_in,
                              void* d_out, int out_size)
{
    const float* x     = (const float*)d_in[0];   // [4,2048,768]
    const float* Wqkv  = (const float*)d_in[1];   // [768,2304]
    const float* Wproj = (const float*)d_in[2];   // [768,768]
    const float* bproj = (const float*)d_in[3];   // [768]
    float* out = (float*)d_out;                   // [4,2048,768]

    float *qkv_ptr, *att_ptr;
    cudaGetSymbolAddress((void**)&qkv_ptr, g_qkv);
    cudaGetSymbolAddress((void**)&att_ptr, g_att);

    // 1) qkv = x @ Wqkv                      [8192,768] x [768,2304]
    dim3 g1(QKVC / 128, ROWS / 128);
    sgemm128<<<g1, 256>>>(x, Wqkv, nullptr, qkv_ptr, ROWS, QKVC, DIM, 0);

    // 2) attention (flash, online softmax)
    dim3 g2(SEQ / 128, BATCH * NHEAD);
    attn_kernel<<<g2, 128>>>();

    // 3) out = att @ Wproj + bproj           [8192,768] x [768,768]
    dim3 g3(DIM / 128, ROWS / 128);
    sgemm128<<<g3, 256>>>(att_ptr, Wproj, bproj, out, ROWS, DIM, DIM, 1);
}

// round 3
// speedup vs baseline: 1.1941x; 1.1941x over previous
#include <cuda_runtime.h>
#include <cstdint>

#define BATCH 4
#define SEQ   2048
#define DIM   768
#define NHEAD 12
#define HDIM  64
#define QKVC  (3*DIM)            // 2304
#define ROWS  (BATCH*SEQ)        // 8192
#define ATT_SCALE 0.125f

// Scratch (allocation-free rule: __device__ globals)
__device__ float g_qkv[(size_t)ROWS * QKVC];   // [B*N, 3*H*D]
__device__ float g_att[(size_t)ROWS * DIM];    // [B*N, H*D]
__device__ float g_Wt1[(size_t)QKVC * DIM];    // Wqkv^T  [2304, 768] (K-major)
__device__ float g_Wt2[(size_t)DIM * DIM];     // Wproj^T [768, 768]

// ---------------------------------------------------------------------------
// tf32 helpers (non-'a' features only: supported on plain sm_103 target)
// ---------------------------------------------------------------------------
__device__ __forceinline__ uint32_t f2tf32(float f) {
    uint32_t r;
    asm("cvt.rna.tf32.f32 %0, %1;" : "=r"(r) : "f"(f));
    return r;
}

// D += A(16x8) * B(8x8), tf32 inputs, fp32 accum
__device__ __forceinline__ void mma16n8k8(float c[4], const uint32_t a[4],
                                          const uint32_t b[2]) {
    asm volatile(
        "mma.sync.aligned.m16n8k8.row.col.f32.tf32.tf32.f32 "
        "{%0,%1,%2,%3}, {%4,%5,%6,%7}, {%8,%9}, {%0,%1,%2,%3};"
        : "+f"(c[0]), "+f"(c[1]), "+f"(c[2]), "+f"(c[3])
        : "r"(a[0]), "r"(a[1]), "r"(a[2]), "r"(a[3]), "r"(b[0]), "r"(b[1]));
}

// ---------------------------------------------------------------------------
// Transpose: dst[c*R + r] = src[r*C + c]   (src: [R, C])
// ---------------------------------------------------------------------------
__global__ void transpose_k(const float* __restrict__ src, float* __restrict__ dst,
                            int R, int C)
{
    __shared__ float t[32][33];
    int bx = blockIdx.x * 32;
    int by = blockIdx.y * 32;
    #pragma unroll
    for (int i = 0; i < 32; i += 8)
        t[threadIdx.y + i][threadIdx.x] =
            src[(size_t)(by + threadIdx.y + i) * C + bx + threadIdx.x];
    __syncthreads();
    #pragma unroll
    for (int i = 0; i < 32; i += 8)
        dst[(size_t)(bx + threadIdx.y + i) * R + by + threadIdx.x] =
            t[threadIdx.x][threadIdx.y + i];
}

// ---------------------------------------------------------------------------
// tf32 mma.sync GEMM:  C[M, Ncols] = A[M, K] @ Bt[Ncols, K]^T  (+ bias)
// 128x128 CTA tile, 8 warps (2x4), 64x32 per warp. K in chunks of 32,
// double-buffered smem, register-staged global prefetch.
// Smem row stride = 36 floats: float4-store friendly AND conflict-free
// fragment reads (bank = gid*4 + tig, all 32 distinct).
// ---------------------------------------------------------------------------
#define KC 32
#define SSTRIDE 36
#define TILE_F (128 * SSTRIDE)     // floats per tile buffer

extern __shared__ float g_smem[];

__global__ __launch_bounds__(256) void gemm_mma(
    const float* __restrict__ A, const float* __restrict__ Bt,
    const float* __restrict__ bias, float* __restrict__ C,
    int Ncols, int K, int addBias)
{
    float* As[2] = { g_smem,              g_smem + 2 * TILE_F };
    float* Bs[2] = { g_smem + TILE_F,     g_smem + 3 * TILE_F };

    const int tid  = threadIdx.x;
    const int lane = tid & 31;
    const int wid  = tid >> 5;
    const int gid  = lane >> 2;      // 0..7
    const int tig  = lane & 3;       // 0..3
    const int wr   = wid >> 2;       // 0..1  warp row
    const int wc   = wid & 3;        // 0..3  warp col
    const int bm = blockIdx.y * 128, bn = blockIdx.x * 128;

    const float* Ag = A  + (size_t)bm * K;
    const float* Bg = Bt + (size_t)bn * K;

    float acc[4][4][4];
    #pragma unroll
    for (int mt = 0; mt < 4; mt++)
        #pragma unroll
        for (int nt = 0; nt < 4; nt++)
            #pragma unroll
            for (int i = 0; i < 4; i++) acc[mt][nt][i] = 0.f;

    float4 pa[4], pb[4];
    const int nch = K / KC;

    // ---- prefetch chunk 0 ----
    #pragma unroll
    for (int i = 0; i < 4; i++) {
        int slot = tid + i * 256;       // 0..1023
        int row  = slot >> 3;
        int q    = slot & 7;
        pa[i] = *(const float4*)(Ag + (size_t)row * K + q * 4);
        pb[i] = *(const float4*)(Bg + (size_t)row * K + q * 4);
    }
    #pragma unroll
    for (int i = 0; i < 4; i++) {
        int slot = tid + i * 256;
        int row  = slot >> 3;
        int q    = slot & 7;
        float* pA = As[0] + row * SSTRIDE + q * 4;
        float* pB = Bs[0] + row * SSTRIDE + q * 4;
        pA[0] = __uint_as_float(f2tf32(pa[i].x));
        pA[1] = __uint_as_float(f2tf32(pa[i].y));
        pA[2] = __uint_as_float(f2tf32(pa[i].z));
        pA[3] = __uint_as_float(f2tf32(pa[i].w));
        pB[0] = __uint_as_float(f2tf32(pb[i].x));
        pB[1] = __uint_as_float(f2tf32(pb[i].y));
        pB[2] = __uint_as_float(f2tf32(pb[i].z));
        pB[3] = __uint_as_float(f2tf32(pb[i].w));
    }
    __syncthreads();

    for (int c = 0; c < nch; c++) {
        const int buf = c & 1;
        // ---- issue global loads for next chunk ----
        if (c + 1 < nch) {
            const float* Agn = Ag + (c + 1) * KC;
            const float* Bgn = Bg + (c + 1) * KC;
            #pragma unroll
            for (int i = 0; i < 4; i++) {
                int slot = tid + i * 256;
                int row  = slot >> 3;
                int q    = slot & 7;
                pa[i] = *(const float4*)(Agn + (size_t)row * K + q * 4);
                pb[i] = *(const float4*)(Bgn + (size_t)row * K + q * 4);
            }
        }

        // ---- compute on current buffer: 4 k8-steps ----
        const uint32_t* Au = (const uint32_t*)As[buf];
        const uint32_t* Bu = (const uint32_t*)Bs[buf];
        #pragma unroll
        for (int ks = 0; ks < 4; ks++) {
            const int k0 = ks * 8;
            uint32_t af[4][4], bf[4][2];
            #pragma unroll
            for (int mt = 0; mt < 4; mt++) {
                int rb = wr * 64 + mt * 16;
                af[mt][0] = Au[(rb + gid)     * SSTRIDE + k0 + tig];
                af[mt][1] = Au[(rb + gid + 8) * SSTRIDE + k0 + tig];
                af[mt][2] = Au[(rb + gid)     * SSTRIDE + k0 + tig + 4];
                af[mt][3] = Au[(rb + gid + 8) * SSTRIDE + k0 + tig + 4];
            }
            #pragma unroll
            for (int nt = 0; nt < 4; nt++) {
                int cb = wc * 32 + nt * 8 + gid;
                bf[nt][0] = Bu[cb * SSTRIDE + k0 + tig];
                bf[nt][1] = Bu[cb * SSTRIDE + k0 + tig + 4];
            }
            #pragma unroll
            for (int mt = 0; mt < 4; mt++)
                #pragma unroll
                for (int nt = 0; nt < 4; nt++)
                    mma16n8k8(acc[mt][nt], af[mt], bf[nt]);
        }

        // ---- store next chunk to the other buffer ----
        if (c + 1 < nch) {
            const int nb = (c + 1) & 1;
            #pragma unroll
            for (int i = 0; i < 4; i++) {
                int slot = tid + i * 256;
                int row  = slot >> 3;
                int q    = slot & 7;
                float* pA = As[nb] + row * SSTRIDE + q * 4;
                float* pB = Bs[nb] + row * SSTRIDE + q * 4;
                pA[0] = __uint_as_float(f2tf32(pa[i].x));
                pA[1] = __uint_as_float(f2tf32(pa[i].y));
                pA[2] = __uint_as_float(f2tf32(pa[i].z));
                pA[3] = __uint_as_float(f2tf32(pa[i].w));
                pB[0] = __uint_as_float(f2tf32(pb[i].x));
                pB[1] = __uint_as_float(f2tf32(pb[i].y));
                pB[2] = __uint_as_float(f2tf32(pb[i].z));
                pB[3] = __uint_as_float(f2tf32(pb[i].w));
            }
        }
        __syncthreads();
    }

    // ---- epilogue ----
    #pragma unroll
    for (int mt = 0; mt < 4; mt++) {
        int r0 = bm + wr * 64 + mt * 16 + gid;
        #pragma unroll
        for (int nt = 0; nt < 4; nt++) {
            int cc = bn + wc * 32 + nt * 8 + tig * 2;
            float b0 = 0.f, b1 = 0.f;
            if (addBias) { b0 = bias[cc]; b1 = bias[cc + 1]; }
            float2 v0 = { acc[mt][nt][0] + b0, acc[mt][nt][1] + b1 };
            float2 v1 = { acc[mt][nt][2] + b0, acc[mt][nt][3] + b1 };
            *(float2*)(C + (size_t)r0 * Ncols + cc)       = v0;
            *(float2*)(C + (size_t)(r0 + 8) * Ncols + cc) = v1;
        }
    }
}

// ---------------------------------------------------------------------------
// Flash-style attention (unchanged): 1 thread = 1 query row.
// ---------------------------------------------------------------------------
__global__ __launch_bounds__(128) void attn_kernel()
{
    const int bh = blockIdx.y;
    const int b  = bh / NHEAD;
    const int h  = bh - b * NHEAD;
    const int qidx = blockIdx.x * 128 + threadIdx.x;

    __shared__ float Ksh[32][64];
    __shared__ float Vsh[32][64];

    float q[64];
    {
        const float* qptr = &g_qkv[((size_t)(b * SEQ + qidx)) * QKVC + h * HDIM];
        #pragma unroll
        for (int d4 = 0; d4 < 16; d4++) {
            float4 v = *(const float4*)(qptr + d4 * 4);
            q[d4 * 4 + 0] = v.x * ATT_SCALE;
            q[d4 * 4 + 1] = v.y * ATT_SCALE;
            q[d4 * 4 + 2] = v.z * ATT_SCALE;
            q[d4 * 4 + 3] = v.w * ATT_SCALE;
        }
    }

    float acc[64];
    #pragma unroll
    for (int d = 0; d < 64; d++) acc[d] = 0.f;
    float m = -1e30f, l = 0.f;

    const float* kbase = &g_qkv[((size_t)(b * SEQ)) * QKVC + DIM + h * HDIM];
    const float* vbase = kbase + DIM;

    for (int k0 = 0; k0 < SEQ; k0 += 32) {
        #pragma unroll
        for (int it = 0; it < 4; it++) {
            int idx = threadIdx.x + it * 128;
            int key = idx >> 4;
            int d4  = idx & 15;
            ((float4*)Ksh)[idx] = *(const float4*)(kbase + (size_t)(k0 + key) * QKVC + d4 * 4);
            ((float4*)Vsh)[idx] = *(const float4*)(vbase + (size_t)(k0 + key) * QKVC + d4 * 4);
        }
        __syncthreads();

        for (int jc = 0; jc < 4; jc++) {
            float s[8];
            #pragma unroll
            for (int j = 0; j < 8; j++) {
                const float4* kr = (const float4*)&Ksh[jc * 8 + j][0];
                float s0 = 0.f, s1 = 0.f, s2 = 0.f, s3 = 0.f;
                #pragma unroll
                for (int d4 = 0; d4 < 16; d4++) {
                    float4 kv = kr[d4];
                    s0 += q[d4 * 4 + 0] * kv.x;
                    s1 += q[d4 * 4 + 1] * kv.y;
                    s2 += q[d4 * 4 + 2] * kv.z;
                    s3 += q[d4 * 4 + 3] * kv.w;
                }
                s[j] = (s0 + s1) + (s2 + s3);
            }
            float tmax = s[0];
            #pragma unroll
            for (int j = 1; j < 8; j++) tmax = fmaxf(tmax, s[j]);
            float m_new = fmaxf(m, tmax);
            float corr = __expf(m - m_new);
            l *= corr;
            #pragma unroll
            for (int d = 0; d < 64; d++) acc[d] *= corr;
            #pragma unroll
            for (int j = 0; j < 8; j++) {
                float p = __expf(s[j] - m_new);
                l += p;
                const float4* vr = (const float4*)&Vsh[jc * 8 + j][0];
                #pragma unroll
                for (int d4 = 0; d4 < 16; d4++) {
                    float4 vv = vr[d4];
                    acc[d4 * 4 + 0] += p * vv.x;
                    acc[d4 * 4 + 1] += p * vv.y;
                    acc[d4 * 4 + 2] += p * vv.z;
                    acc[d4 * 4 + 3] += p * vv.w;
                }
            }
            m = m_new;
        }
        __syncthreads();
    }

    const float inv = 1.f / l;
    float* optr = &g_att[((size_t)(b * SEQ + qidx)) * DIM + h * HDIM];
    #pragma unroll
    for (int d4 = 0; d4 < 16; d4++) {
        float4 v;
        v.x = acc[d4 * 4 + 0] * inv;
        v.y = acc[d4 * 4 + 1] * inv;
        v.z = acc[d4 * 4 + 2] * inv;
        v.w = acc[d4 * 4 + 3] * inv;
        *(float4*)(optr + d4 * 4) = v;
    }
}

// ---------------------------------------------------------------------------
extern "C" void kernel_launch(void* const* d_in, const int* in_sizes, int n_in,
                              void* d_out, int out_size)
{
    const float* x     = (const float*)d_in[0];   // [4,2048,768]
    const float* Wqkv  = (const float*)d_in[1];   // [768,2304]
    const float* Wproj = (const float*)d_in[2];   // [768,768]
    const float* bproj = (const float*)d_in[3];   // [768]
    float* out = (float*)d_out;

    float *qkv_ptr, *att_ptr, *wt1_ptr, *wt2_ptr;
    cudaGetSymbolAddress((void**)&qkv_ptr, g_qkv);
    cudaGetSymbolAddress((void**)&att_ptr, g_att);
    cudaGetSymbolAddress((void**)&wt1_ptr, g_Wt1);
    cudaGetSymbolAddress((void**)&wt2_ptr, g_Wt2);

    const int smem_bytes = 4 * TILE_F * sizeof(float);   // 73728
    static int configured = 0;
    cudaFuncSetAttribute(gemm_mma, cudaFuncAttributeMaxDynamicSharedMemorySize,
                         smem_bytes);
    (void)configured;

    // 0) transpose weights to K-major
    transpose_k<<<dim3(QKVC / 32, DIM / 32), dim3(32, 8)>>>(Wqkv, wt1_ptr, DIM, QKVC);
    transpose_k<<<dim3(DIM / 32, DIM / 32), dim3(32, 8)>>>(Wproj, wt2_ptr, DIM, DIM);

    // 1) qkv = x @ Wqkv            (tf32 mma.sync)
    gemm_mma<<<dim3(QKVC / 128, ROWS / 128), 256, smem_bytes>>>(
        x, wt1_ptr, nullptr, qkv_ptr, QKVC, DIM, 0);

    // 2) attention
    attn_kernel<<<dim3(SEQ / 128, BATCH * NHEAD), 128>>>();

    // 3) out = att @ Wproj + bproj (tf32 mma.sync)
    gemm_mma<<<dim3(DIM / 128, ROWS / 128), 256, smem_bytes>>>(
        att_ptr, wt2_ptr, bproj, out, DIM, DIM, 1);
}

// round 4
// speedup vs baseline: 2.5023x; 2.0956x over previous
#include <cuda_runtime.h>
#include <cstdint>

#define BATCH 4
#define SEQ   2048
#define DIM   768
#define NHEAD 12
#define HDIM  64
#define QKVC  (3*DIM)            // 2304
#define ROWS  (BATCH*SEQ)        // 8192
#define ATT_SCALE 0.125f

// Scratch (allocation-free rule: __device__ globals)
__device__ float g_qkv[(size_t)ROWS * QKVC];   // [B*N, 3*H*D]
__device__ float g_att[(size_t)ROWS * DIM];    // [B*N, H*D]
__device__ float g_Wt1[(size_t)QKVC * DIM];    // Wqkv^T  [2304, 768] (K-major)
__device__ float g_Wt2[(size_t)DIM * DIM];     // Wproj^T [768, 768]

// ---------------------------------------------------------------------------
// tf32 helpers (non-'a' features only: supported on plain sm_103 target)
// ---------------------------------------------------------------------------
__device__ __forceinline__ uint32_t f2tf32(float f) {
    uint32_t r;
    asm("cvt.rna.tf32.f32 %0, %1;" : "=r"(r) : "f"(f));
    return r;
}

// D += A(16x8) * B(8x8), tf32 inputs, fp32 accum
__device__ __forceinline__ void mma16n8k8(float c[4], const uint32_t a[4],
                                          const uint32_t b[2]) {
    asm volatile(
        "mma.sync.aligned.m16n8k8.row.col.f32.tf32.tf32.f32 "
        "{%0,%1,%2,%3}, {%4,%5,%6,%7}, {%8,%9}, {%0,%1,%2,%3};"
        : "+f"(c[0]), "+f"(c[1]), "+f"(c[2]), "+f"(c[3])
        : "r"(a[0]), "r"(a[1]), "r"(a[2]), "r"(a[3]), "r"(b[0]), "r"(b[1]));
}

// ---------------------------------------------------------------------------
// Transpose: dst[c*R + r] = src[r*C + c]   (src: [R, C])
// ---------------------------------------------------------------------------
__global__ void transpose_k(const float* __restrict__ src, float* __restrict__ dst,
                            int R, int C)
{
    __shared__ float t[32][33];
    int bx = blockIdx.x * 32;
    int by = blockIdx.y * 32;
    #pragma unroll
    for (int i = 0; i < 32; i += 8)
        t[threadIdx.y + i][threadIdx.x] =
            src[(size_t)(by + threadIdx.y + i) * C + bx + threadIdx.x];
    __syncthreads();
    #pragma unroll
    for (int i = 0; i < 32; i += 8)
        dst[(size_t)(bx + threadIdx.y + i) * R + by + threadIdx.x] =
            t[threadIdx.x][threadIdx.y + i];
}

// ---------------------------------------------------------------------------
// tf32 mma.sync GEMM (unchanged from round 3)
// ---------------------------------------------------------------------------
#define KC 32
#define SSTRIDE 36
#define TILE_F (128 * SSTRIDE)

extern __shared__ float g_smem[];

__global__ __launch_bounds__(256) void gemm_mma(
    const float* __restrict__ A, const float* __restrict__ Bt,
    const float* __restrict__ bias, float* __restrict__ C,
    int Ncols, int K, int addBias)
{
    float* As[2] = { g_smem,              g_smem + 2 * TILE_F };
    float* Bs[2] = { g_smem + TILE_F,     g_smem + 3 * TILE_F };

    const int tid  = threadIdx.x;
    const int lane = tid & 31;
    const int wid  = tid >> 5;
    const int gid  = lane >> 2;
    const int tig  = lane & 3;
    const int wr   = wid >> 2;
    const int wc   = wid & 3;
    const int bm = blockIdx.y * 128, bn = blockIdx.x * 128;

    const float* Ag = A  + (size_t)bm * K;
    const float* Bg = Bt + (size_t)bn * K;

    float acc[4][4][4];
    #pragma unroll
    for (int mt = 0; mt < 4; mt++)
        #pragma unroll
        for (int nt = 0; nt < 4; nt++)
            #pragma unroll
            for (int i = 0; i < 4; i++) acc[mt][nt][i] = 0.f;

    float4 pa[4], pb[4];
    const int nch = K / KC;

    #pragma unroll
    for (int i = 0; i < 4; i++) {
        int slot = tid + i * 256;
        int row  = slot >> 3;
        int q    = slot & 7;
        pa[i] = *(const float4*)(Ag + (size_t)row * K + q * 4);
        pb[i] = *(const float4*)(Bg + (size_t)row * K + q * 4);
    }
    #pragma unroll
    for (int i = 0; i < 4; i++) {
        int slot = tid + i * 256;
        int row  = slot >> 3;
        int q    = slot & 7;
        float* pA = As[0] + row * SSTRIDE + q * 4;
        float* pB = Bs[0] + row * SSTRIDE + q * 4;
        pA[0] = __uint_as_float(f2tf32(pa[i].x));
        pA[1] = __uint_as_float(f2tf32(pa[i].y));
        pA[2] = __uint_as_float(f2tf32(pa[i].z));
        pA[3] = __uint_as_float(f2tf32(pa[i].w));
        pB[0] = __uint_as_float(f2tf32(pb[i].x));
        pB[1] = __uint_as_float(f2tf32(pb[i].y));
        pB[2] = __uint_as_float(f2tf32(pb[i].z));
        pB[3] = __uint_as_float(f2tf32(pb[i].w));
    }
    __syncthreads();

    for (int c = 0; c < nch; c++) {
        const int buf = c & 1;
        if (c + 1 < nch) {
            const float* Agn = Ag + (c + 1) * KC;
            const float* Bgn = Bg + (c + 1) * KC;
            #pragma unroll
            for (int i = 0; i < 4; i++) {
                int slot = tid + i * 256;
                int row  = slot >> 3;
                int q    = slot & 7;
                pa[i] = *(const float4*)(Agn + (size_t)row * K + q * 4);
                pb[i] = *(const float4*)(Bgn + (size_t)row * K + q * 4);
            }
        }

        const uint32_t* Au = (const uint32_t*)As[buf];
        const uint32_t* Bu = (const uint32_t*)Bs[buf];
        #pragma unroll
        for (int ks = 0; ks < 4; ks++) {
            const int k0 = ks * 8;
            uint32_t af[4][4], bf[4][2];
            #pragma unroll
            for (int mt = 0; mt < 4; mt++) {
                int rb = wr * 64 + mt * 16;
                af[mt][0] = Au[(rb + gid)     * SSTRIDE + k0 + tig];
                af[mt][1] = Au[(rb + gid + 8) * SSTRIDE + k0 + tig];
                af[mt][2] = Au[(rb + gid)     * SSTRIDE + k0 + tig + 4];
                af[mt][3] = Au[(rb + gid + 8) * SSTRIDE + k0 + tig + 4];
            }
            #pragma unroll
            for (int nt = 0; nt < 4; nt++) {
                int cb = wc * 32 + nt * 8 + gid;
                bf[nt][0] = Bu[cb * SSTRIDE + k0 + tig];
                bf[nt][1] = Bu[cb * SSTRIDE + k0 + tig + 4];
            }
            #pragma unroll
            for (int mt = 0; mt < 4; mt++)
                #pragma unroll
                for (int nt = 0; nt < 4; nt++)
                    mma16n8k8(acc[mt][nt], af[mt], bf[nt]);
        }

        if (c + 1 < nch) {
            const int nb = (c + 1) & 1;
            #pragma unroll
            for (int i = 0; i < 4; i++) {
                int slot = tid + i * 256;
                int row  = slot >> 3;
                int q    = slot & 7;
                float* pA = As[nb] + row * SSTRIDE + q * 4;
                float* pB = Bs[nb] + row * SSTRIDE + q * 4;
                pA[0] = __uint_as_float(f2tf32(pa[i].x));
                pA[1] = __uint_as_float(f2tf32(pa[i].y));
                pA[2] = __uint_as_float(f2tf32(pa[i].z));
                pA[3] = __uint_as_float(f2tf32(pa[i].w));
                pB[0] = __uint_as_float(f2tf32(pb[i].x));
                pB[1] = __uint_as_float(f2tf32(pb[i].y));
                pB[2] = __uint_as_float(f2tf32(pb[i].z));
                pB[3] = __uint_as_float(f2tf32(pb[i].w));
            }
        }
        __syncthreads();
    }

    #pragma unroll
    for (int mt = 0; mt < 4; mt++) {
        int r0 = bm + wr * 64 + mt * 16 + gid;
        #pragma unroll
        for (int nt = 0; nt < 4; nt++) {
            int cc = bn + wc * 32 + nt * 8 + tig * 2;
            float b0 = 0.f, b1 = 0.f;
            if (addBias) { b0 = bias[cc]; b1 = bias[cc + 1]; }
            float2 v0 = { acc[mt][nt][0] + b0, acc[mt][nt][1] + b1 };
            float2 v1 = { acc[mt][nt][2] + b0, acc[mt][nt][3] + b1 };
            *(float2*)(C + (size_t)r0 * Ncols + cc)       = v0;
            *(float2*)(C + (size_t)(r0 + 8) * Ncols + cc) = v1;
        }
    }
}

// ---------------------------------------------------------------------------
// Tensor-core flash attention (tf32 mma.sync).
// CTA: 128 queries x 1 (batch,head). 8 warps x 16 query rows.
// Q in registers as A-fragments (loaded once). Per 64-key tile:
//   stage K,V (tf32) in smem (stride 72 -> conflict-free fragment loads),
//   S = Q@K^T via MMA, in-register online softmax (quad shfl reductions),
//   P staged through smem (C-frag -> A-frag layout), O += P@V via MMA.
// Smem: Ks 64x72, Vs 64x72, Ss 128x72 floats = 73728 B.
// ---------------------------------------------------------------------------
#define AST 72
#define KT  64                      // keys per tile

__global__ __launch_bounds__(256) void attn_mma()
{
    float* Ks = g_smem;                    // [64][72]
    float* Vs = g_smem + 64 * AST;         // [64][72]
    float* Ss = g_smem + 128 * AST;        // [128][72]

    const int tid  = threadIdx.x;
    const int lane = tid & 31;
    const int wid  = tid >> 5;          // 0..7
    const int gid  = lane >> 2;         // 0..7
    const int tig  = lane & 3;          // 0..3
    const int wb   = wid * 16;          // warp's query-row base within tile

    const int bh = blockIdx.y;
    const int b  = bh / NHEAD;
    const int h  = bh - b * NHEAD;
    const int qbase = blockIdx.x * 128;

    const float* kbase = g_qkv + (size_t)(b * SEQ) * QKVC + DIM + h * HDIM;
    const float* vbase = kbase + DIM;

    // ---- Q fragments (A operand), pre-scaled, tf32 ----
    uint32_t qf[8][4];
    {
        const float* Qg = g_qkv + (size_t)(b * SEQ + qbase + wb) * QKVC + h * HDIM;
        #pragma unroll
        for (int ks = 0; ks < 8; ks++) {
            int k0 = ks * 8;
            qf[ks][0] = f2tf32(Qg[(size_t)gid       * QKVC + k0 + tig]     * ATT_SCALE);
            qf[ks][1] = f2tf32(Qg[(size_t)(gid + 8) * QKVC + k0 + tig]     * ATT_SCALE);
            qf[ks][2] = f2tf32(Qg[(size_t)gid       * QKVC + k0 + tig + 4] * ATT_SCALE);
            qf[ks][3] = f2tf32(Qg[(size_t)(gid + 8) * QKVC + k0 + tig + 4] * ATT_SCALE);
        }
    }

    float of[8][4];
    #pragma unroll
    for (int nt = 0; nt < 8; nt++)
        #pragma unroll
        for (int i = 0; i < 4; i++) of[nt][i] = 0.f;
    float m0 = -1e30f, m1 = -1e30f, l0 = 0.f, l1 = 0.f;

    for (int kt = 0; kt < SEQ; kt += KT) {
        // ---- stage K,V tile (tf32) ----
        #pragma unroll
        for (int i = 0; i < 4; i++) {
            int slot = tid + i * 256;        // 0..1023
            int row  = slot >> 4;            // key 0..63
            int q    = slot & 15;            // float4 within 64 floats
            float4 kv = *(const float4*)(kbase + (size_t)(kt + row) * QKVC + q * 4);
            float4 vv = *(const float4*)(vbase + (size_t)(kt + row) * QKVC + q * 4);
            float4 tk, tv;
            tk.x = __uint_as_float(f2tf32(kv.x));
            tk.y = __uint_as_float(f2tf32(kv.y));
            tk.z = __uint_as_float(f2tf32(kv.z));
            tk.w = __uint_as_float(f2tf32(kv.w));
            tv.x = __uint_as_float(f2tf32(vv.x));
            tv.y = __uint_as_float(f2tf32(vv.y));
            tv.z = __uint_as_float(f2tf32(vv.z));
            tv.w = __uint_as_float(f2tf32(vv.w));
            *(float4*)(Ks + row * AST + q * 4) = tk;
            *(float4*)(Vs + row * AST + q * 4) = tv;
        }
        __syncthreads();

        // ---- S = Q @ K^T  (per warp: 16 x 64) ----
        float sc[8][4];
        #pragma unroll
        for (int nt = 0; nt < 8; nt++)
            #pragma unroll
            for (int i = 0; i < 4; i++) sc[nt][i] = 0.f;

        const uint32_t* Ku = (const uint32_t*)Ks;
        #pragma unroll
        for (int ks = 0; ks < 8; ks++) {
            const int k0 = ks * 8;
            #pragma unroll
            for (int nt = 0; nt < 8; nt++) {
                uint32_t bf[2];
                bf[0] = Ku[(nt * 8 + gid) * AST + k0 + tig];
                bf[1] = Ku[(nt * 8 + gid) * AST + k0 + tig + 4];
                mma16n8k8(sc[nt], qf[ks], bf);
            }
        }

        // ---- online softmax (in-register, quad reductions) ----
        float tm0 = -1e30f, tm1 = -1e30f;
        #pragma unroll
        for (int nt = 0; nt < 8; nt++) {
            tm0 = fmaxf(tm0, fmaxf(sc[nt][0], sc[nt][1]));
            tm1 = fmaxf(tm1, fmaxf(sc[nt][2], sc[nt][3]));
        }
        tm0 = fmaxf(tm0, __shfl_xor_sync(0xffffffffu, tm0, 1));
        tm0 = fmaxf(tm0, __shfl_xor_sync(0xffffffffu, tm0, 2));
        tm1 = fmaxf(tm1, __shfl_xor_sync(0xffffffffu, tm1, 1));
        tm1 = fmaxf(tm1, __shfl_xor_sync(0xffffffffu, tm1, 2));

        float m0n = fmaxf(m0, tm0);
        float m1n = fmaxf(m1, tm1);
        float c0 = __expf(m0 - m0n);
        float c1 = __expf(m1 - m1n);

        float s0 = 0.f, s1 = 0.f;
        #pragma unroll
        for (int nt = 0; nt < 8; nt++) {
            sc[nt][0] = __expf(sc[nt][0] - m0n);
            sc[nt][1] = __expf(sc[nt][1] - m0n);
            sc[nt][2] = __expf(sc[nt][2] - m1n);
            sc[nt][3] = __expf(sc[nt][3] - m1n);
            s0 += sc[nt][0] + sc[nt][1];
            s1 += sc[nt][2] + sc[nt][3];
        }
        s0 += __shfl_xor_sync(0xffffffffu, s0, 1);
        s0 += __shfl_xor_sync(0xffffffffu, s0, 2);
        s1 += __shfl_xor_sync(0xffffffffu, s1, 1);
        s1 += __shfl_xor_sync(0xffffffffu, s1, 2);

        l0 = l0 * c0 + s0;
        l1 = l1 * c1 + s1;
        m0 = m0n; m1 = m1n;

        #pragma unroll
        for (int nt = 0; nt < 8; nt++) {
            of[nt][0] *= c0; of[nt][1] *= c0;
            of[nt][2] *= c1; of[nt][3] *= c1;
        }

        // ---- stage P (tf32) via smem for layout conversion (warp-private rows)
        #pragma unroll
        for (int nt = 0; nt < 8; nt++) {
            float2 p0 = { __uint_as_float(f2tf32(sc[nt][0])),
                          __uint_as_float(f2tf32(sc[nt][1])) };
            float2 p1 = { __uint_as_float(f2tf32(sc[nt][2])),
                          __uint_as_float(f2tf32(sc[nt][3])) };
            *(float2*)(Ss + (wb + gid)     * AST + nt * 8 + tig * 2) = p0;
            *(float2*)(Ss + (wb + gid + 8) * AST + nt * 8 + tig * 2) = p1;
        }
        __syncwarp();

        // ---- O += P @ V ----
        const uint32_t* Pu = (const uint32_t*)Ss;
        const uint32_t* Vu = (const uint32_t*)Vs;
        #pragma unroll
        for (int ks = 0; ks < 8; ks++) {
            const int k0 = ks * 8;
            uint32_t af[4];
            af[0] = Pu[(wb + gid)     * AST + k0 + tig];
            af[1] = Pu[(wb + gid + 8) * AST + k0 + tig];
            af[2] = Pu[(wb + gid)     * AST + k0 + tig + 4];
            af[3] = Pu[(wb + gid + 8) * AST + k0 + tig + 4];
            #pragma unroll
            for (int nt = 0; nt < 8; nt++) {
                uint32_t bf[2];
                bf[0] = Vu[(k0 + tig)     * AST + nt * 8 + gid];
                bf[1] = Vu[(k0 + tig + 4) * AST + nt * 8 + gid];
                mma16n8k8(of[nt], af, bf);
            }
        }
        __syncthreads();
    }

    // ---- epilogue ----
    const float inv0 = 1.f / l0;
    const float inv1 = 1.f / l1;
    const int r0 = b * SEQ + qbase + wb + gid;
    #pragma unroll
    for (int nt = 0; nt < 8; nt++) {
        int col = h * HDIM + nt * 8 + tig * 2;
        float2 v0 = { of[nt][0] * inv0, of[nt][1] * inv0 };
        float2 v1 = { of[nt][2] * inv1, of[nt][3] * inv1 };
        *(float2*)(g_att + (size_t)r0 * DIM + col)       = v0;
        *(float2*)(g_att + (size_t)(r0 + 8) * DIM + col) = v1;
    }
}

// ---------------------------------------------------------------------------
extern "C" void kernel_launch(void* const* d_in, const int* in_sizes, int n_in,
                              void* d_out, int out_size)
{
    const float* x     = (const float*)d_in[0];   // [4,2048,768]
    const float* Wqkv  = (const float*)d_in[1];   // [768,2304]
    const float* Wproj = (const float*)d_in[2];   // [768,768]
    const float* bproj = (const float*)d_in[3];   // [768]
    float* out = (float*)d_out;

    float *qkv_ptr, *att_ptr, *wt1_ptr, *wt2_ptr;
    cudaGetSymbolAddress((void**)&qkv_ptr, g_qkv);
    cudaGetSymbolAddress((void**)&att_ptr, g_att);
    cudaGetSymbolAddress((void**)&wt1_ptr, g_Wt1);
    cudaGetSymbolAddress((void**)&wt2_ptr, g_Wt2);

    const int smem_gemm = 4 * TILE_F * sizeof(float);        // 73728
    const int smem_attn = (64 + 64 + 128) * AST * sizeof(float);  // 73728
    cudaFuncSetAttribute(gemm_mma, cudaFuncAttributeMaxDynamicSharedMemorySize,
                         smem_gemm);
    cudaFuncSetAttribute(attn_mma, cudaFuncAttributeMaxDynamicSharedMemorySize,
                         smem_attn);

    // 0) transpose weights to K-major
    transpose_k<<<dim3(QKVC / 32, DIM / 32), dim3(32, 8)>>>(Wqkv, wt1_ptr, DIM, QKVC);
    transpose_k<<<dim3(DIM / 32, DIM / 32), dim3(32, 8)>>>(Wproj, wt2_ptr, DIM, DIM);

    // 1) qkv = x @ Wqkv            (tf32 mma.sync)
    gemm_mma<<<dim3(QKVC / 128, ROWS / 128), 256, smem_gemm>>>(
        x, wt1_ptr, nullptr, qkv_ptr, QKVC, DIM, 0);

    // 2) attention (tensor-core flash)
    attn_mma<<<dim3(SEQ / 128, BATCH * NHEAD), 256, smem_attn>>>();

    // 3) out = att @ Wproj + bproj (tf32 mma.sync)
    gemm_mma<<<dim3(DIM / 128, ROWS / 128), 256, smem_gemm>>>(
        att_ptr, wt2_ptr, bproj, out, DIM, DIM, 1);
}

// round 5
// speedup vs baseline: 2.6769x; 1.0698x over previous
#include <cuda_runtime.h>
#include <cstdint>

#define BATCH 4
#define SEQ   2048
#define DIM   768
#define NHEAD 12
#define HDIM  64
#define QKVC  (3*DIM)            // 2304
#define ROWS  (BATCH*SEQ)        // 8192
#define ATT_SCALE 0.125f
#define LOG2E 1.44269504088896340736f

// Scratch (allocation-free rule: __device__ globals)
__device__ float g_qkv[(size_t)ROWS * QKVC];   // [B*N, 3*H*D]
__device__ float g_att[(size_t)ROWS * DIM];    // [B*N, H*D]
__device__ float g_Wt1[(size_t)QKVC * DIM];    // Wqkv^T  [2304, 768] (K-major)
__device__ float g_Wt2[(size_t)DIM * DIM];     // Wproj^T [768, 768]

// ---------------------------------------------------------------------------
// helpers (non-'a' features only: supported on plain sm_103 target)
// ---------------------------------------------------------------------------
__device__ __forceinline__ uint32_t f2tf32(float f) {
    uint32_t r;
    asm("cvt.rna.tf32.f32 %0, %1;" : "=r"(r) : "f"(f));
    return r;
}
__device__ __forceinline__ float ex2(float x) {
    float r;
    asm("ex2.approx.ftz.f32 %0, %1;" : "=f"(r) : "f"(x));
    return r;
}
__device__ __forceinline__ uint32_t smem_u32(const void* p) {
    uint32_t a;
    asm("{ .reg .u64 t; cvta.to.shared.u64 t, %1; cvt.u32.u64 %0, t; }"
        : "=r"(a) : "l"(p));
    return a;
}
__device__ __forceinline__ void cp_async16(uint32_t saddr, const void* gptr) {
    asm volatile("cp.async.cg.shared.global [%0], [%1], 16;"
                 :: "r"(saddr), "l"(gptr) : "memory");
}
#define CP_COMMIT() asm volatile("cp.async.commit_group;" ::: "memory")
#define CP_WAIT(n)  asm volatile("cp.async.wait_group %0;" :: "n"(n) : "memory")

// D += A(16x8) * B(8x8), tf32 inputs, fp32 accum
__device__ __forceinline__ void mma16n8k8(float c[4], const uint32_t a[4],
                                          const uint32_t b[2]) {
    asm volatile(
        "mma.sync.aligned.m16n8k8.row.col.f32.tf32.tf32.f32 "
        "{%0,%1,%2,%3}, {%4,%5,%6,%7}, {%8,%9}, {%0,%1,%2,%3};"
        : "+f"(c[0]), "+f"(c[1]), "+f"(c[2]), "+f"(c[3])
        : "r"(a[0]), "r"(a[1]), "r"(a[2]), "r"(a[3]), "r"(b[0]), "r"(b[1]));
}

// ---------------------------------------------------------------------------
// Transpose: dst[c*R + r] = src[r*C + c]   (src: [R, C])
// ---------------------------------------------------------------------------
__global__ void transpose_k(const float* __restrict__ src, float* __restrict__ dst,
                            int R, int C)
{
    __shared__ float t[32][33];
    int bx = blockIdx.x * 32;
    int by = blockIdx.y * 32;
    #pragma unroll
    for (int i = 0; i < 32; i += 8)
        t[threadIdx.y + i][threadIdx.x] =
            src[(size_t)(by + threadIdx.y + i) * C + bx + threadIdx.x];
    __syncthreads();
    #pragma unroll
    for (int i = 0; i < 32; i += 8)
        dst[(size_t)(bx + threadIdx.y + i) * R + by + threadIdx.x] =
            t[threadIdx.x][threadIdx.y + i];
}

// ---------------------------------------------------------------------------
// tf32 mma.sync GEMM (unchanged from round 3)
// ---------------------------------------------------------------------------
#define KC 32
#define SSTRIDE 36
#define TILE_F (128 * SSTRIDE)

extern __shared__ float g_smem[];

__global__ __launch_bounds__(256) void gemm_mma(
    const float* __restrict__ A, const float* __restrict__ Bt,
    const float* __restrict__ bias, float* __restrict__ C,
    int Ncols, int K, int addBias)
{
    float* As[2] = { g_smem,              g_smem + 2 * TILE_F };
    float* Bs[2] = { g_smem + TILE_F,     g_smem + 3 * TILE_F };

    const int tid  = threadIdx.x;
    const int lane = tid & 31;
    const int wid  = tid >> 5;
    const int gid  = lane >> 2;
    const int tig  = lane & 3;
    const int wr   = wid >> 2;
    const int wc   = wid & 3;
    const int bm = blockIdx.y * 128, bn = blockIdx.x * 128;

    const float* Ag = A  + (size_t)bm * K;
    const float* Bg = Bt + (size_t)bn * K;

    float acc[4][4][4];
    #pragma unroll
    for (int mt = 0; mt < 4; mt++)
        #pragma unroll
        for (int nt = 0; nt < 4; nt++)
            #pragma unroll
            for (int i = 0; i < 4; i++) acc[mt][nt][i] = 0.f;

    float4 pa[4], pb[4];
    const int nch = K / KC;

    #pragma unroll
    for (int i = 0; i < 4; i++) {
        int slot = tid + i * 256;
        int row  = slot >> 3;
        int q    = slot & 7;
        pa[i] = *(const float4*)(Ag + (size_t)row * K + q * 4);
        pb[i] = *(const float4*)(Bg + (size_t)row * K + q * 4);
    }
    #pragma unroll
    for (int i = 0; i < 4; i++) {
        int slot = tid + i * 256;
        int row  = slot >> 3;
        int q    = slot & 7;
        float* pA = As[0] + row * SSTRIDE + q * 4;
        float* pB = Bs[0] + row * SSTRIDE + q * 4;
        pA[0] = __uint_as_float(f2tf32(pa[i].x));
        pA[1] = __uint_as_float(f2tf32(pa[i].y));
        pA[2] = __uint_as_float(f2tf32(pa[i].z));
        pA[3] = __uint_as_float(f2tf32(pa[i].w));
        pB[0] = __uint_as_float(f2tf32(pb[i].x));
        pB[1] = __uint_as_float(f2tf32(pb[i].y));
        pB[2] = __uint_as_float(f2tf32(pb[i].z));
        pB[3] = __uint_as_float(f2tf32(pb[i].w));
    }
    __syncthreads();

    for (int c = 0; c < nch; c++) {
        const int buf = c & 1;
        if (c + 1 < nch) {
            const float* Agn = Ag + (c + 1) * KC;
            const float* Bgn = Bg + (c + 1) * KC;
            #pragma unroll
            for (int i = 0; i < 4; i++) {
                int slot = tid + i * 256;
                int row  = slot >> 3;
                int q    = slot & 7;
                pa[i] = *(const float4*)(Agn + (size_t)row * K + q * 4);
                pb[i] = *(const float4*)(Bgn + (size_t)row * K + q * 4);
            }
        }

        const uint32_t* Au = (const uint32_t*)As[buf];
        const uint32_t* Bu = (const uint32_t*)Bs[buf];
        #pragma unroll
        for (int ks = 0; ks < 4; ks++) {
            const int k0 = ks * 8;
            uint32_t af[4][4], bf[4][2];
            #pragma unroll
            for (int mt = 0; mt < 4; mt++) {
                int rb = wr * 64 + mt * 16;
                af[mt][0] = Au[(rb + gid)     * SSTRIDE + k0 + tig];
                af[mt][1] = Au[(rb + gid + 8) * SSTRIDE + k0 + tig];
                af[mt][2] = Au[(rb + gid)     * SSTRIDE + k0 + tig + 4];
                af[mt][3] = Au[(rb + gid + 8) * SSTRIDE + k0 + tig + 4];
            }
            #pragma unroll
            for (int nt = 0; nt < 4; nt++) {
                int cb = wc * 32 + nt * 8 + gid;
                bf[nt][0] = Bu[cb * SSTRIDE + k0 + tig];
                bf[nt][1] = Bu[cb * SSTRIDE + k0 + tig + 4];
            }
            #pragma unroll
            for (int mt = 0; mt < 4; mt++)
                #pragma unroll
                for (int nt = 0; nt < 4; nt++)
                    mma16n8k8(acc[mt][nt], af[mt], bf[nt]);
        }

        if (c + 1 < nch) {
            const int nb = (c + 1) & 1;
            #pragma unroll
            for (int i = 0; i < 4; i++) {
                int slot = tid + i * 256;
                int row  = slot >> 3;
                int q    = slot & 7;
                float* pA = As[nb] + row * SSTRIDE + q * 4;
                float* pB = Bs[nb] + row * SSTRIDE + q * 4;
                pA[0] = __uint_as_float(f2tf32(pa[i].x));
                pA[1] = __uint_as_float(f2tf32(pa[i].y));
                pA[2] = __uint_as_float(f2tf32(pa[i].z));
                pA[3] = __uint_as_float(f2tf32(pa[i].w));
                pB[0] = __uint_as_float(f2tf32(pb[i].x));
                pB[1] = __uint_as_float(f2tf32(pb[i].y));
                pB[2] = __uint_as_float(f2tf32(pb[i].z));
                pB[3] = __uint_as_float(f2tf32(pb[i].w));
            }
        }
        __syncthreads();
    }

    #pragma unroll
    for (int mt = 0; mt < 4; mt++) {
        int r0 = bm + wr * 64 + mt * 16 + gid;
        #pragma unroll
        for (int nt = 0; nt < 4; nt++) {
            int cc = bn + wc * 32 + nt * 8 + tig * 2;
            float b0 = 0.f, b1 = 0.f;
            if (addBias) { b0 = bias[cc]; b1 = bias[cc + 1]; }
            float2 v0 = { acc[mt][nt][0] + b0, acc[mt][nt][1] + b1 };
            float2 v1 = { acc[mt][nt][2] + b0, acc[mt][nt][3] + b1 };
            *(float2*)(C + (size_t)r0 * Ncols + cc)       = v0;
            *(float2*)(C + (size_t)(r0 + 8) * Ncols + cc) = v1;
        }
    }
}

// ---------------------------------------------------------------------------
// Tensor-core flash attention, v2:
//  - cp.async double-buffered K/V (raw fp32; tf32 cvt moved to fragment load)
//  - 2 CTAs/SM (launch_bounds reg cap)
//  - exp2-domain softmax (log2e folded into Q scale)
// Smem: KV[2][128][72] + Ss[128][72] floats = 110592 B.
// ---------------------------------------------------------------------------
#define AST 72
#define KT  64
#define NTILES (SEQ / KT)

__global__ __launch_bounds__(256, 2) void attn_mma()
{
    float* KV[2] = { g_smem, g_smem + 128 * AST };      // K rows 0..63, V rows 64..127
    float* Ss    = g_smem + 2 * 128 * AST;              // [128][72]

    const int tid  = threadIdx.x;
    const int lane = tid & 31;
    const int wid  = tid >> 5;          // 0..7
    const int gid  = lane >> 2;         // 0..7
    const int tig  = lane & 3;          // 0..3
    const int wb   = wid * 16;

    const int bh = blockIdx.y;
    const int b  = bh / NHEAD;
    const int h  = bh - b * NHEAD;
    const int qbase = blockIdx.x * 128;

    const float* kbase = g_qkv + (size_t)(b * SEQ) * QKVC + DIM + h * HDIM;
    const float* vbase = kbase + DIM;

    // staging addresses (this thread's 4 slots)
    const int srow = tid >> 4;           // 0..15 within 4-slot stride pattern
    const int sq   = tid & 15;
    uint32_t kv_s[2][2];                 // [buf][k/v] smem u32 base for slot 0
    #pragma unroll
    for (int bu = 0; bu < 2; bu++) {
        kv_s[bu][0] = smem_u32(KV[bu] + srow * AST + sq * 4);
        kv_s[bu][1] = smem_u32(KV[bu] + (64 + srow) * AST + sq * 4);
    }

    // ---- Q fragments (A operand), scaled by ATT_SCALE*log2e, tf32 ----
    uint32_t qf[8][4];
    {
        const float qs = ATT_SCALE * LOG2E;
        const float* Qg = g_qkv + (size_t)(b * SEQ + qbase + wb) * QKVC + h * HDIM;
        #pragma unroll
        for (int ks = 0; ks < 8; ks++) {
            int k0 = ks * 8;
            qf[ks][0] = f2tf32(Qg[(size_t)gid       * QKVC + k0 + tig]     * qs);
            qf[ks][1] = f2tf32(Qg[(size_t)(gid + 8) * QKVC + k0 + tig]     * qs);
            qf[ks][2] = f2tf32(Qg[(size_t)gid       * QKVC + k0 + tig + 4] * qs);
            qf[ks][3] = f2tf32(Qg[(size_t)(gid + 8) * QKVC + k0 + tig + 4] * qs);
        }
    }

    float of[8][4];
    #pragma unroll
    for (int nt = 0; nt < 8; nt++)
        #pragma unroll
        for (int i = 0; i < 4; i++) of[nt][i] = 0.f;
    float m0 = -1e30f, m1 = -1e30f, l0 = 0.f, l1 = 0.f;

    // ---- stage tile 0 ----
    #pragma unroll
    for (int i = 0; i < 4; i++) {
        int row = srow + i * 16;
        cp_async16(kv_s[0][0] + i * 16 * AST * 4,
                   kbase + (size_t)row * QKVC + sq * 4);
        cp_async16(kv_s[0][1] + i * 16 * AST * 4,
                   vbase + (size_t)row * QKVC + sq * 4);
    }
    CP_COMMIT();

    for (int t = 0; t < NTILES; t++) {
        const int buf = t & 1;
        if (t + 1 < NTILES) {
            const int nb = buf ^ 1;
            const int kt = (t + 1) * KT;
            #pragma unroll
            for (int i = 0; i < 4; i++) {
                int row = srow + i * 16;
                cp_async16(kv_s[nb][0] + i * 16 * AST * 4,
                           kbase + (size_t)(kt + row) * QKVC + sq * 4);
                cp_async16(kv_s[nb][1] + i * 16 * AST * 4,
                           vbase + (size_t)(kt + row) * QKVC + sq * 4);
            }
            CP_COMMIT();
            CP_WAIT(1);
        } else {
            CP_WAIT(0);
        }
        __syncthreads();

        const float* Ksb = KV[buf];
        const float* Vsb = KV[buf] + 64 * AST;

        // ---- S = Q @ K^T (cvt to tf32 at load) ----
        float sc[8][4];
        #pragma unroll
        for (int nt = 0; nt < 8; nt++)
            #pragma unroll
            for (int i = 0; i < 4; i++) sc[nt][i] = 0.f;

        #pragma unroll
        for (int ks = 0; ks < 8; ks++) {
            const int k0 = ks * 8;
            #pragma unroll
            for (int nt = 0; nt < 8; nt++) {
                uint32_t bf[2];
                bf[0] = f2tf32(Ksb[(nt * 8 + gid) * AST + k0 + tig]);
                bf[1] = f2tf32(Ksb[(nt * 8 + gid) * AST + k0 + tig + 4]);
                mma16n8k8(sc[nt], qf[ks], bf);
            }
        }

        // ---- online softmax (log2 domain, quad shfl reductions) ----
        float tm0 = -1e30f, tm1 = -1e30f;
        #pragma unroll
        for (int nt = 0; nt < 8; nt++) {
            tm0 = fmaxf(tm0, fmaxf(sc[nt][0], sc[nt][1]));
            tm1 = fmaxf(tm1, fmaxf(sc[nt][2], sc[nt][3]));
        }
        tm0 = fmaxf(tm0, __shfl_xor_sync(0xffffffffu, tm0, 1));
        tm0 = fmaxf(tm0, __shfl_xor_sync(0xffffffffu, tm0, 2));
        tm1 = fmaxf(tm1, __shfl_xor_sync(0xffffffffu, tm1, 1));
        tm1 = fmaxf(tm1, __shfl_xor_sync(0xffffffffu, tm1, 2));

        float m0n = fmaxf(m0, tm0);
        float m1n = fmaxf(m1, tm1);
        float c0 = ex2(m0 - m0n);
        float c1 = ex2(m1 - m1n);

        float s0 = 0.f, s1 = 0.f;
        #pragma unroll
        for (int nt = 0; nt < 8; nt++) {
            sc[nt][0] = ex2(sc[nt][0] - m0n);
            sc[nt][1] = ex2(sc[nt][1] - m0n);
            sc[nt][2] = ex2(sc[nt][2] - m1n);
            sc[nt][3] = ex2(sc[nt][3] - m1n);
            s0 += sc[nt][0] + sc[nt][1];
            s1 += sc[nt][2] + sc[nt][3];
        }
        s0 += __shfl_xor_sync(0xffffffffu, s0, 1);
        s0 += __shfl_xor_sync(0xffffffffu, s0, 2);
        s1 += __shfl_xor_sync(0xffffffffu, s1, 1);
        s1 += __shfl_xor_sync(0xffffffffu, s1, 2);

        l0 = l0 * c0 + s0;
        l1 = l1 * c1 + s1;
        m0 = m0n; m1 = m1n;

        #pragma unroll
        for (int nt = 0; nt < 8; nt++) {
            of[nt][0] *= c0; of[nt][1] *= c0;
            of[nt][2] *= c1; of[nt][3] *= c1;
        }

        // ---- stage P (tf32) via smem (warp-private rows) ----
        #pragma unroll
        for (int nt = 0; nt < 8; nt++) {
            float2 p0 = { __uint_as_float(f2tf32(sc[nt][0])),
                          __uint_as_float(f2tf32(sc[nt][1])) };
            float2 p1 = { __uint_as_float(f2tf32(sc[nt][2])),
                          __uint_as_float(f2tf32(sc[nt][3])) };
            *(float2*)(Ss + (wb + gid)     * AST + nt * 8 + tig * 2) = p0;
            *(float2*)(Ss + (wb + gid + 8) * AST + nt * 8 + tig * 2) = p1;
        }
        __syncwarp();

        // ---- O += P @ V (cvt V to tf32 at load) ----
        const uint32_t* Pu = (const uint32_t*)Ss;
        #pragma unroll
        for (int ks = 0; ks < 8; ks++) {
            const int k0 = ks * 8;
            uint32_t af[4];
            af[0] = Pu[(wb + gid)     * AST + k0 + tig];
            af[1] = Pu[(wb + gid + 8) * AST + k0 + tig];
            af[2] = Pu[(wb + gid)     * AST + k0 + tig + 4];
            af[3] = Pu[(wb + gid + 8) * AST + k0 + tig + 4];
            #pragma unroll
            for (int nt = 0; nt < 8; nt++) {
                uint32_t bf[2];
                bf[0] = f2tf32(Vsb[(k0 + tig)     * AST + nt * 8 + gid]);
                bf[1] = f2tf32(Vsb[(k0 + tig + 4) * AST + nt * 8 + gid]);
                mma16n8k8(of[nt], af, bf);
            }
        }
        __syncthreads();   // all warps done with buf before it is restaged
    }

    // ---- epilogue ----
    const float inv0 = 1.f / l0;
    const float inv1 = 1.f / l1;
    const int r0 = b * SEQ + qbase + wb + gid;
    #pragma unroll
    for (int nt = 0; nt < 8; nt++) {
        int col = h * HDIM + nt * 8 + tig * 2;
        float2 v0 = { of[nt][0] * inv0, of[nt][1] * inv0 };
        float2 v1 = { of[nt][2] * inv1, of[nt][3] * inv1 };
        *(float2*)(g_att + (size_t)r0 * DIM + col)       = v0;
        *(float2*)(g_att + (size_t)(r0 + 8) * DIM + col) = v1;
    }
}

// ---------------------------------------------------------------------------
extern "C" void kernel_launch(void* const* d_in, const int* in_sizes, int n_in,
                              void* d_out, int out_size)
{
    const float* x     = (const float*)d_in[0];   // [4,2048,768]
    const float* Wqkv  = (const float*)d_in[1];   // [768,2304]
    const float* Wproj = (const float*)d_in[2];   // [768,768]
    const float* bproj = (const float*)d_in[3];   // [768]
    float* out = (float*)d_out;

    float *qkv_ptr, *att_ptr, *wt1_ptr, *wt2_ptr;
    cudaGetSymbolAddress((void**)&qkv_ptr, g_qkv);
    cudaGetSymbolAddress((void**)&att_ptr, g_att);
    cudaGetSymbolAddress((void**)&wt1_ptr, g_Wt1);
    cudaGetSymbolAddress((void**)&wt2_ptr, g_Wt2);

    const int smem_gemm = 4 * TILE_F * sizeof(float);              // 73728
    const int smem_attn = (2 * 128 + 128) * AST * sizeof(float);   // 110592
    cudaFuncSetAttribute(gemm_mma, cudaFuncAttributeMaxDynamicSharedMemorySize,
                         smem_gemm);
    cudaFuncSetAttribute(attn_mma, cudaFuncAttributeMaxDynamicSharedMemorySize,
                         smem_attn);

    // 0) transpose weights to K-major
    transpose_k<<<dim3(QKVC / 32, DIM / 32), dim3(32, 8)>>>(Wqkv, wt1_ptr, DIM, QKVC);
    transpose_k<<<dim3(DIM / 32, DIM / 32), dim3(32, 8)>>>(Wproj, wt2_ptr, DIM, DIM);

    // 1) qkv = x @ Wqkv            (tf32 mma.sync)
    gemm_mma<<<dim3(QKVC / 128, ROWS / 128), 256, smem_gemm>>>(
        x, wt1_ptr, nullptr, qkv_ptr, QKVC, DIM, 0);

    // 2) attention (tensor-core flash, pipelined)
    attn_mma<<<dim3(SEQ / 128, BATCH * NHEAD), 256, smem_attn>>>();

    // 3) out = att @ Wproj + bproj (tf32 mma.sync)
    gemm_mma<<<dim3(DIM / 128, ROWS / 128), 256, smem_gemm>>>(
        att_ptr, wt2_ptr, bproj, out, DIM, DIM, 1);
}